// round 1
// baseline (speedup 1.0000x reference)
#include <cuda_runtime.h>
#include <math.h>

#define B_   2
#define T_   2048
#define D_   1024
#define H_   16
#define HKV_ 4
#define HD_  64
#define KV_  256
#define BT_  (B_ * T_)
#define EPS_ 1.1920928955078125e-07f
#define SP   68   // padded smem row stride (floats) for flash tiles

// ---------------- scratch (static device globals; no runtime alloc) --------
__device__ float g_qraw[BT_ * D_];          // [BT, 1024] raw q projection
__device__ float g_kraw[BT_ * KV_];         // [BT, 256]
__device__ float g_vraw[BT_ * KV_];         // [BT, 256]
__device__ float g_q[B_ * H_ * T_ * HD_];   // [B,H,T,hd] normed+rope+gain+scale
__device__ float g_k[B_ * HKV_ * T_ * HD_]; // [B,Hkv,T,hd] normed+rope
__device__ float g_v[B_ * HKV_ * T_ * HD_]; // [B,Hkv,T,hd]
__device__ float g_y[BT_ * D_];             // attention output [BT, 1024]
__device__ float g_invf[32];                // rope inv_freq table

// ---------------- inv_freq table (double pow once) -------------------------
__global__ void k_freq() {
    int i = threadIdx.x;
    if (i < 32) g_invf[i] = (float)pow(10000.0, -(double)i / 32.0);
}

// ---------------- generic fp32 GEMM: C[m,n] = sum_k A[m,k] * W[n,k] --------
// Tiles 128x128x16, 256 threads, 8x8 per thread. M,N,K multiples of 128/16.
__device__ __forceinline__ void gemm_body(const float* __restrict__ A,
                                          const float* __restrict__ W,
                                          float* __restrict__ C, int K) {
    __shared__ float As[16][128];
    __shared__ float Bs[16][128];
    const int tid = threadIdx.x;
    const int ty = tid >> 4, tx = tid & 15;
    const int bm = blockIdx.y * 128, bn = blockIdx.x * 128;
    const int N = gridDim.x * 128;
    float acc[8][8];
#pragma unroll
    for (int i = 0; i < 8; i++)
#pragma unroll
        for (int j = 0; j < 8; j++) acc[i][j] = 0.0f;

    const int lr = tid >> 1;
    const int lc = (tid & 1) * 8;
    const float* Ap = A + (size_t)(bm + lr) * K + lc;
    const float* Wp = W + (size_t)(bn + lr) * K + lc;

    for (int k0 = 0; k0 < K; k0 += 16) {
        float4 a0 = *(const float4*)(Ap + k0);
        float4 a1 = *(const float4*)(Ap + k0 + 4);
        float4 b0 = *(const float4*)(Wp + k0);
        float4 b1 = *(const float4*)(Wp + k0 + 4);
        __syncthreads();
        As[lc + 0][lr] = a0.x; As[lc + 1][lr] = a0.y;
        As[lc + 2][lr] = a0.z; As[lc + 3][lr] = a0.w;
        As[lc + 4][lr] = a1.x; As[lc + 5][lr] = a1.y;
        As[lc + 6][lr] = a1.z; As[lc + 7][lr] = a1.w;
        Bs[lc + 0][lr] = b0.x; Bs[lc + 1][lr] = b0.y;
        Bs[lc + 2][lr] = b0.z; Bs[lc + 3][lr] = b0.w;
        Bs[lc + 4][lr] = b1.x; Bs[lc + 5][lr] = b1.y;
        Bs[lc + 6][lr] = b1.z; Bs[lc + 7][lr] = b1.w;
        __syncthreads();
#pragma unroll
        for (int kk = 0; kk < 16; kk++) {
            float ar[8], br[8];
            *(float4*)(ar)     = *(const float4*)&As[kk][ty * 8];
            *(float4*)(ar + 4) = *(const float4*)&As[kk][ty * 8 + 4];
            *(float4*)(br)     = *(const float4*)&Bs[kk][tx * 8];
            *(float4*)(br + 4) = *(const float4*)&Bs[kk][tx * 8 + 4];
#pragma unroll
            for (int i = 0; i < 8; i++)
#pragma unroll
                for (int j = 0; j < 8; j++)
                    acc[i][j] = fmaf(ar[i], br[j], acc[i][j]);
        }
    }
#pragma unroll
    for (int i = 0; i < 8; i++) {
        float* cp = C + (size_t)(bm + ty * 8 + i) * N + bn + tx * 8;
        *(float4*)cp       = make_float4(acc[i][0], acc[i][1], acc[i][2], acc[i][3]);
        *(float4*)(cp + 4) = make_float4(acc[i][4], acc[i][5], acc[i][6], acc[i][7]);
    }
}

__global__ void __launch_bounds__(256) k_gemm_q(const float* __restrict__ x,
                                                const float* __restrict__ W) {
    gemm_body(x, W, g_qraw, D_);
}
__global__ void __launch_bounds__(256) k_gemm_k(const float* __restrict__ x,
                                                const float* __restrict__ W) {
    gemm_body(x, W, g_kraw, D_);
}
__global__ void __launch_bounds__(256) k_gemm_v(const float* __restrict__ x,
                                                const float* __restrict__ W) {
    gemm_body(x, W, g_vraw, D_);
}
__global__ void __launch_bounds__(256) k_gemm_o(const float* __restrict__ W,
                                                float* __restrict__ out) {
    gemm_body(g_y, W, out, D_);
}

// ---------------- RMSNorm + RoPE (+gain*scale for q), one warp per head ----
__global__ void __launch_bounds__(256) k_qprep(const float* __restrict__ gain) {
    int wid = (blockIdx.x * blockDim.x + threadIdx.x) >> 5;
    int lane = threadIdx.x & 31;
    int h = wid & (H_ - 1);
    int t = (wid >> 4) & (T_ - 1);
    int b = wid >> 15;
    const float* src = g_qraw + (size_t)(b * T_ + t) * D_ + h * HD_;
    float x1 = src[lane], x2 = src[lane + 32];
    float ss = x1 * x1 + x2 * x2;
#pragma unroll
    for (int o = 16; o > 0; o >>= 1) ss += __shfl_xor_sync(0xffffffffu, ss, o);
    float r = rsqrtf(ss * (1.0f / 64.0f) + EPS_);
    x1 *= r; x2 *= r;
    float f = (float)t * g_invf[lane];
    float s, c;
    sincosf(f, &s, &c);
    float g = gain[h] * 0.125f;  // fold attention scale hd^-0.5 into q
    float* dst = g_q + ((size_t)(b * H_ + h) * T_ + t) * HD_;
    dst[lane]      = (x1 * c + x2 * s) * g;
    dst[lane + 32] = (x2 * c - x1 * s) * g;
}

__global__ void __launch_bounds__(256) k_kprep() {
    int wid = (blockIdx.x * blockDim.x + threadIdx.x) >> 5;
    int lane = threadIdx.x & 31;
    int h = wid & (HKV_ - 1);
    int t = (wid >> 2) & (T_ - 1);
    int b = wid >> 13;
    const float* src = g_kraw + (size_t)(b * T_ + t) * KV_ + h * HD_;
    float x1 = src[lane], x2 = src[lane + 32];
    float ss = x1 * x1 + x2 * x2;
#pragma unroll
    for (int o = 16; o > 0; o >>= 1) ss += __shfl_xor_sync(0xffffffffu, ss, o);
    float r = rsqrtf(ss * (1.0f / 64.0f) + EPS_);
    x1 *= r; x2 *= r;
    float f = (float)t * g_invf[lane];
    float s, c;
    sincosf(f, &s, &c);
    float* dst = g_k + ((size_t)(b * HKV_ + h) * T_ + t) * HD_;
    dst[lane]      = x1 * c + x2 * s;
    dst[lane + 32] = x2 * c - x1 * s;
}

__global__ void __launch_bounds__(256) k_vtrans() {
    int i = blockIdx.x * blockDim.x + threadIdx.x;  // over B*HKV*T*16 float4s
    int d4 = i & 15;
    int t = (i >> 4) & (T_ - 1);
    int hk = (i >> 15) & (HKV_ - 1);
    int b = i >> 17;
    const float4* s = (const float4*)(g_vraw + (size_t)(b * T_ + t) * KV_ + hk * HD_) + d4;
    float4* d = (float4*)(g_v + ((size_t)(b * HKV_ + hk) * T_ + t) * HD_) + d4;
    *d = *s;
}

// ---------------- flash attention, BQ=BN=64, fp32 --------------------------
extern __shared__ float sh_flash[];

__global__ void __launch_bounds__(256, 3) k_flash() {
    float* Qt = sh_flash;                // [64][SP] transposed (d-major)
    float* Kt = sh_flash + 64 * SP;      // [64][SP] transposed (d-major)
    float* Vs = sh_flash + 2 * 64 * SP;  // [64][SP] natural (k-major)
    float* Pn = sh_flash + 3 * 64 * SP;  // [64][SP] natural (row-major P)

    const int tid = threadIdx.x;
    const int ty = tid >> 4, tx = tid & 15;
    const int qb = (int)gridDim.x - 1 - (int)blockIdx.x;  // heavy blocks first
    const int h = blockIdx.y, b = blockIdx.z;
    const int hkv = h >> 2;

    const float* Qg = g_q + ((size_t)(b * H_ + h) * T_ + qb * 64) * HD_;
    const float* Kg = g_k + (size_t)(b * HKV_ + hkv) * T_ * HD_;
    const float* Vg = g_v + (size_t)(b * HKV_ + hkv) * T_ * HD_;

    const int lr = tid >> 2;
    const int lc = (tid & 3) * 16;
    {
        const float* p = Qg + lr * 64 + lc;
        float4 v0 = *(const float4*)p;
        float4 v1 = *(const float4*)(p + 4);
        float4 v2 = *(const float4*)(p + 8);
        float4 v3 = *(const float4*)(p + 12);
        Qt[(lc + 0) * SP + lr] = v0.x;  Qt[(lc + 1) * SP + lr] = v0.y;
        Qt[(lc + 2) * SP + lr] = v0.z;  Qt[(lc + 3) * SP + lr] = v0.w;
        Qt[(lc + 4) * SP + lr] = v1.x;  Qt[(lc + 5) * SP + lr] = v1.y;
        Qt[(lc + 6) * SP + lr] = v1.z;  Qt[(lc + 7) * SP + lr] = v1.w;
        Qt[(lc + 8) * SP + lr] = v2.x;  Qt[(lc + 9) * SP + lr] = v2.y;
        Qt[(lc + 10) * SP + lr] = v2.z; Qt[(lc + 11) * SP + lr] = v2.w;
        Qt[(lc + 12) * SP + lr] = v3.x; Qt[(lc + 13) * SP + lr] = v3.y;
        Qt[(lc + 14) * SP + lr] = v3.z; Qt[(lc + 15) * SP + lr] = v3.w;
    }

    float m[4], l[4], o[4][4];
#pragma unroll
    for (int i = 0; i < 4; i++) {
        m[i] = -1e30f; l[i] = 0.0f;
#pragma unroll
        for (int j = 0; j < 4; j++) o[i][j] = 0.0f;
    }

    for (int kb = 0; kb <= qb; kb++) {
        const float* kp = Kg + (size_t)(kb * 64 + lr) * 64 + lc;
        const float* vp = Vg + (size_t)(kb * 64 + lr) * 64 + lc;
        float4 k0 = *(const float4*)kp;
        float4 k1 = *(const float4*)(kp + 4);
        float4 k2 = *(const float4*)(kp + 8);
        float4 k3 = *(const float4*)(kp + 12);
        float4 w0 = *(const float4*)vp;
        float4 w1 = *(const float4*)(vp + 4);
        float4 w2 = *(const float4*)(vp + 8);
        float4 w3 = *(const float4*)(vp + 12);
        __syncthreads();  // prior iteration done reading Kt/Vs/Pn
        Kt[(lc + 0) * SP + lr] = k0.x;  Kt[(lc + 1) * SP + lr] = k0.y;
        Kt[(lc + 2) * SP + lr] = k0.z;  Kt[(lc + 3) * SP + lr] = k0.w;
        Kt[(lc + 4) * SP + lr] = k1.x;  Kt[(lc + 5) * SP + lr] = k1.y;
        Kt[(lc + 6) * SP + lr] = k1.z;  Kt[(lc + 7) * SP + lr] = k1.w;
        Kt[(lc + 8) * SP + lr] = k2.x;  Kt[(lc + 9) * SP + lr] = k2.y;
        Kt[(lc + 10) * SP + lr] = k2.z; Kt[(lc + 11) * SP + lr] = k2.w;
        Kt[(lc + 12) * SP + lr] = k3.x; Kt[(lc + 13) * SP + lr] = k3.y;
        Kt[(lc + 14) * SP + lr] = k3.z; Kt[(lc + 15) * SP + lr] = k3.w;
        *(float4*)&Vs[lr * SP + lc]      = w0;
        *(float4*)&Vs[lr * SP + lc + 4]  = w1;
        *(float4*)&Vs[lr * SP + lc + 8]  = w2;
        *(float4*)&Vs[lr * SP + lc + 12] = w3;
        __syncthreads();

        // S = Q @ K^T   (scale+gain already folded into Q)
        float s[4][4];
#pragma unroll
        for (int i = 0; i < 4; i++)
#pragma unroll
            for (int j = 0; j < 4; j++) s[i][j] = 0.0f;
#pragma unroll 8
        for (int d = 0; d < 64; d++) {
            float qr[4], kr[4];
            *(float4*)qr = *(const float4*)&Qt[d * SP + 4 * ty];
            *(float4*)kr = *(const float4*)&Kt[d * SP + 4 * tx];
#pragma unroll
            for (int i = 0; i < 4; i++)
#pragma unroll
                for (int j = 0; j < 4; j++)
                    s[i][j] = fmaf(qr[i], kr[j], s[i][j]);
        }

        if (kb == qb) {
#pragma unroll
            for (int i = 0; i < 4; i++)
#pragma unroll
                for (int j = 0; j < 4; j++)
                    if (4 * tx + j > 4 * ty + i) s[i][j] = -1e30f;
        }

        // online softmax (rows owned by the 16 lanes sharing ty)
#pragma unroll
        for (int i = 0; i < 4; i++) {
            float mx = fmaxf(fmaxf(s[i][0], s[i][1]), fmaxf(s[i][2], s[i][3]));
#pragma unroll
            for (int off = 8; off > 0; off >>= 1)
                mx = fmaxf(mx, __shfl_xor_sync(0xffffffffu, mx, off));
            float mn = fmaxf(m[i], mx);
            float corr = __expf(m[i] - mn);
            float p0 = __expf(s[i][0] - mn);
            float p1 = __expf(s[i][1] - mn);
            float p2 = __expf(s[i][2] - mn);
            float p3 = __expf(s[i][3] - mn);
            float rs = p0 + p1 + p2 + p3;
#pragma unroll
            for (int off = 8; off > 0; off >>= 1)
                rs += __shfl_xor_sync(0xffffffffu, rs, off);
            l[i] = l[i] * corr + rs;
            m[i] = mn;
            o[i][0] *= corr; o[i][1] *= corr; o[i][2] *= corr; o[i][3] *= corr;
            *(float4*)&Pn[(4 * ty + i) * SP + 4 * tx] = make_float4(p0, p1, p2, p3);
        }
        __syncthreads();

        // O += P @ V
#pragma unroll 4
        for (int kk = 0; kk < 64; kk++) {
            float pr[4], vr[4];
            pr[0] = Pn[(4 * ty + 0) * SP + kk];
            pr[1] = Pn[(4 * ty + 1) * SP + kk];
            pr[2] = Pn[(4 * ty + 2) * SP + kk];
            pr[3] = Pn[(4 * ty + 3) * SP + kk];
            *(float4*)vr = *(const float4*)&Vs[kk * SP + 4 * tx];
#pragma unroll
            for (int i = 0; i < 4; i++)
#pragma unroll
                for (int j = 0; j < 4; j++)
                    o[i][j] = fmaf(pr[i], vr[j], o[i][j]);
        }
    }

#pragma unroll
    for (int i = 0; i < 4; i++) {
        float inv = 1.0f / l[i];
        int t = qb * 64 + 4 * ty + i;
        *(float4*)&g_y[(size_t)(b * T_ + t) * D_ + h * HD_ + 4 * tx] =
            make_float4(o[i][0] * inv, o[i][1] * inv, o[i][2] * inv, o[i][3] * inv);
    }
}

// ---------------- launch ----------------------------------------------------
extern "C" void kernel_launch(void* const* d_in, const int* in_sizes, int n_in,
                              void* d_out, int out_size) {
    const float* x    = (const float*)d_in[0];
    const float* Wq   = (const float*)d_in[1];
    const float* Wk   = (const float*)d_in[2];
    const float* Wv   = (const float*)d_in[3];
    const float* Wp   = (const float*)d_in[4];
    const float* gain = (const float*)d_in[5];
    float* out = (float*)d_out;

    k_freq<<<1, 32>>>();
    k_gemm_q<<<dim3(D_ / 128, BT_ / 128), 256>>>(x, Wq);
    k_gemm_k<<<dim3(KV_ / 128, BT_ / 128), 256>>>(x, Wk);
    k_gemm_v<<<dim3(KV_ / 128, BT_ / 128), 256>>>(x, Wv);
    k_qprep<<<(B_ * T_ * H_) / 8, 256>>>(gain);
    k_kprep<<<(B_ * T_ * HKV_) / 8, 256>>>();
    k_vtrans<<<(B_ * HKV_ * T_ * 16) / 256, 256>>>();

    int flash_smem = 4 * 64 * SP * (int)sizeof(float);  // 69632 bytes
    cudaFuncSetAttribute(k_flash, cudaFuncAttributeMaxDynamicSharedMemorySize,
                         flash_smem);
    k_flash<<<dim3(T_ / 64, H_, B_), 256, flash_smem>>>();

    k_gemm_o<<<dim3(D_ / 128, BT_ / 128), 256>>>(Wp, out);
}

// round 3
// speedup vs baseline: 1.5465x; 1.5465x over previous
#include <cuda_runtime.h>
#include <math.h>

#define B_   2
#define T_   2048
#define D_   1024
#define H_   16
#define HKV_ 4
#define HD_  64
#define KV_  256
#define BT_  (B_ * T_)
#define EPS_ 1.1920928955078125e-07f
#define SP   68   // padded smem row stride (floats) for flash tiles
#define KT   32   // gemm K-tile
#define AST  36   // gemm smem row stride (tf32 words)

// ---------------- scratch (static device globals; no runtime alloc) --------
__device__ float g_qraw[BT_ * D_];          // [BT, 1024] raw q projection
__device__ float g_kraw[BT_ * KV_];         // [BT, 256]
__device__ float g_vraw[BT_ * KV_];         // [BT, 256]
__device__ float g_q[B_ * H_ * T_ * HD_];   // [B,H,T,hd] normed+rope+gain+scale
__device__ float g_k[B_ * HKV_ * T_ * HD_]; // [B,Hkv,T,hd] normed+rope
__device__ float g_v[B_ * HKV_ * T_ * HD_]; // [B,Hkv,T,hd]
__device__ float g_y[BT_ * D_];             // attention output [BT, 1024]
__device__ float g_invf[32];                // rope inv_freq table

// ---------------- inv_freq table (double pow once) -------------------------
__global__ void k_freq() {
    int i = threadIdx.x;
    if (i < 32) g_invf[i] = (float)pow(10000.0, -(double)i / 32.0);
}

// ---------------- tf32 helpers ---------------------------------------------
__device__ __forceinline__ unsigned f2tf(float f) {
    unsigned r;
    asm("cvt.rna.tf32.f32 %0, %1;" : "=r"(r) : "f"(f));
    return r;
}

__device__ __forceinline__ void mma_tf32(float c[4], unsigned a0, unsigned a1,
                                         unsigned a2, unsigned a3,
                                         unsigned b0, unsigned b1) {
    asm volatile(
        "mma.sync.aligned.m16n8k8.row.col.f32.tf32.tf32.f32 "
        "{%0,%1,%2,%3}, {%4,%5,%6,%7}, {%8,%9}, {%0,%1,%2,%3};"
        : "+f"(c[0]), "+f"(c[1]), "+f"(c[2]), "+f"(c[3])
        : "r"(a0), "r"(a1), "r"(a2), "r"(a3), "r"(b0), "r"(b1));
}

// ---------------- tf32 tensor-core GEMM: C[m,n] = sum_k A[m,k]*W[n,k] ------
// Block tile 128x128xKT(32), 256 threads = 8 warps (2M x 4N), warp 64x32.
__device__ __forceinline__ void gemm_tf32(const float* __restrict__ A,
                                          const float* __restrict__ W,
                                          float* __restrict__ C,
                                          int K, int N, int bm, int bn) {
    __shared__ unsigned As[128 * AST];
    __shared__ unsigned Ws[128 * AST];
    const int tid  = threadIdx.x;
    const int lane = tid & 31;
    const int w    = tid >> 5;
    const int g    = lane >> 2;     // 0..7
    const int tig  = lane & 3;      // 0..3
    const int wm   = (w & 1) * 64;  // warp M offset in tile
    const int wn   = (w >> 1) * 32; // warp N offset in tile

    const int lr  = tid >> 1;          // 0..127 loader row
    const int lcH = (tid & 1) * 16;    // loader col half
    const float* Ap = A + (size_t)(bm + lr) * K + lcH;
    const float* Wp = W + (size_t)(bn + lr) * K + lcH;

    float acc[4][4][4];
#pragma unroll
    for (int mi = 0; mi < 4; mi++)
#pragma unroll
        for (int ni = 0; ni < 4; ni++)
#pragma unroll
            for (int r = 0; r < 4; r++) acc[mi][ni][r] = 0.0f;

    for (int k0 = 0; k0 < K; k0 += KT) {
        float4 av[4], wv[4];
#pragma unroll
        for (int i = 0; i < 4; i++) {
            av[i] = *(const float4*)(Ap + k0 + 4 * i);
            wv[i] = *(const float4*)(Wp + k0 + 4 * i);
        }
        __syncthreads();
#pragma unroll
        for (int i = 0; i < 4; i++) {
            unsigned* pa = &As[lr * AST + lcH + 4 * i];
            pa[0] = f2tf(av[i].x); pa[1] = f2tf(av[i].y);
            pa[2] = f2tf(av[i].z); pa[3] = f2tf(av[i].w);
            unsigned* pw = &Ws[lr * AST + lcH + 4 * i];
            pw[0] = f2tf(wv[i].x); pw[1] = f2tf(wv[i].y);
            pw[2] = f2tf(wv[i].z); pw[3] = f2tf(wv[i].w);
        }
        __syncthreads();
#pragma unroll
        for (int ks = 0; ks < KT / 8; ks++) {
            unsigned bfr[4][2];
#pragma unroll
            for (int ni = 0; ni < 4; ni++) {
                int r = (wn + ni * 8 + g) * AST + ks * 8 + tig;
                bfr[ni][0] = Ws[r];
                bfr[ni][1] = Ws[r + 4];
            }
#pragma unroll
            for (int mi = 0; mi < 4; mi++) {
                int r = (wm + mi * 16 + g) * AST + ks * 8 + tig;
                unsigned a0 = As[r];
                unsigned a2 = As[r + 4];
                unsigned a1 = As[r + 8 * AST];
                unsigned a3 = As[r + 8 * AST + 4];
#pragma unroll
                for (int ni = 0; ni < 4; ni++)
                    mma_tf32(acc[mi][ni], a0, a1, a2, a3,
                             bfr[ni][0], bfr[ni][1]);
            }
        }
    }

#pragma unroll
    for (int mi = 0; mi < 4; mi++) {
#pragma unroll
        for (int ni = 0; ni < 4; ni++) {
            int row = bm + wm + mi * 16 + g;
            int col = bn + wn + ni * 8 + 2 * tig;
            *(float2*)&C[(size_t)row * N + col] =
                make_float2(acc[mi][ni][0], acc[mi][ni][1]);
            *(float2*)&C[(size_t)(row + 8) * N + col] =
                make_float2(acc[mi][ni][2], acc[mi][ni][3]);
        }
    }
}

__global__ void __launch_bounds__(256) k_gemm_q(const float* __restrict__ x,
                                                const float* __restrict__ W) {
    gemm_tf32(x, W, g_qraw, D_, D_, blockIdx.y * 128, blockIdx.x * 128);
}
// K and V projections fused into one launch (grid.x: 0,1 -> K ; 2,3 -> V)
__global__ void __launch_bounds__(256) k_gemm_kv(const float* __restrict__ x,
                                                 const float* __restrict__ Wk,
                                                 const float* __restrict__ Wv) {
    int bx = blockIdx.x;
    const float* W = (bx < 2) ? Wk : Wv;
    float* C = (bx < 2) ? g_kraw : g_vraw;
    int bn = (bx & 1) * 128;
    gemm_tf32(x, W, C, D_, KV_, blockIdx.y * 128, bn);
}
__global__ void __launch_bounds__(256) k_gemm_o(const float* __restrict__ W,
                                                float* __restrict__ out) {
    gemm_tf32(g_y, W, out, D_, D_, blockIdx.y * 128, blockIdx.x * 128);
}

// ---------------- RMSNorm + RoPE (+gain*scale for q), one warp per head ----
__global__ void __launch_bounds__(256) k_qprep(const float* __restrict__ gain) {
    int wid = (blockIdx.x * blockDim.x + threadIdx.x) >> 5;
    int lane = threadIdx.x & 31;
    int h = wid & (H_ - 1);
    int t = (wid >> 4) & (T_ - 1);
    int b = wid >> 15;
    const float* src = g_qraw + (size_t)(b * T_ + t) * D_ + h * HD_;
    float x1 = src[lane], x2 = src[lane + 32];
    float ss = x1 * x1 + x2 * x2;
#pragma unroll
    for (int o = 16; o > 0; o >>= 1) ss += __shfl_xor_sync(0xffffffffu, ss, o);
    float r = rsqrtf(ss * (1.0f / 64.0f) + EPS_);
    x1 *= r; x2 *= r;
    float f = (float)t * g_invf[lane];
    float s, c;
    sincosf(f, &s, &c);
    float g = gain[h] * 0.125f;  // fold attention scale hd^-0.5 into q
    float* dst = g_q + ((size_t)(b * H_ + h) * T_ + t) * HD_;
    dst[lane]      = (x1 * c + x2 * s) * g;
    dst[lane + 32] = (x2 * c - x1 * s) * g;
}

__global__ void __launch_bounds__(256) k_kprep() {
    int wid = (blockIdx.x * blockDim.x + threadIdx.x) >> 5;
    int lane = threadIdx.x & 31;
    int h = wid & (HKV_ - 1);
    int t = (wid >> 2) & (T_ - 1);
    int b = wid >> 13;
    const float* src = g_kraw + (size_t)(b * T_ + t) * KV_ + h * HD_;
    float x1 = src[lane], x2 = src[lane + 32];
    float ss = x1 * x1 + x2 * x2;
#pragma unroll
    for (int o = 16; o > 0; o >>= 1) ss += __shfl_xor_sync(0xffffffffu, ss, o);
    float r = rsqrtf(ss * (1.0f / 64.0f) + EPS_);
    x1 *= r; x2 *= r;
    float f = (float)t * g_invf[lane];
    float s, c;
    sincosf(f, &s, &c);
    float* dst = g_k + ((size_t)(b * HKV_ + h) * T_ + t) * HD_;
    dst[lane]      = x1 * c + x2 * s;
    dst[lane + 32] = x2 * c - x1 * s;
}

__global__ void __launch_bounds__(256) k_vtrans() {
    int i = blockIdx.x * blockDim.x + threadIdx.x;  // over B*HKV*T*16 float4s
    int d4 = i & 15;
    int t = (i >> 4) & (T_ - 1);
    int hk = (i >> 15) & (HKV_ - 1);
    int b = i >> 17;
    const float4* s = (const float4*)(g_vraw + (size_t)(b * T_ + t) * KV_ + hk * HD_) + d4;
    float4* d = (float4*)(g_v + ((size_t)(b * HKV_ + hk) * T_ + t) * HD_) + d4;
    *d = *s;
}

// ---------------- flash attention, BQ=BN=64, fp32 --------------------------
extern __shared__ float sh_flash[];

__global__ void __launch_bounds__(256, 3) k_flash() {
    float* Qt = sh_flash;                // [64][SP] transposed (d-major)
    float* Kt = sh_flash + 64 * SP;      // [64][SP] transposed (d-major)
    float* Vs = sh_flash + 2 * 64 * SP;  // [64][SP] natural (k-major)
    float* Pn = sh_flash + 3 * 64 * SP;  // [64][SP] natural (row-major P)

    const int tid = threadIdx.x;
    const int ty = tid >> 4, tx = tid & 15;
    const int qb = (int)gridDim.x - 1 - (int)blockIdx.x;  // heavy blocks first
    const int h = blockIdx.y, b = blockIdx.z;
    const int hkv = h >> 2;

    const float* Qg = g_q + ((size_t)(b * H_ + h) * T_ + qb * 64) * HD_;
    const float* Kg = g_k + (size_t)(b * HKV_ + hkv) * T_ * HD_;
    const float* Vg = g_v + (size_t)(b * HKV_ + hkv) * T_ * HD_;

    const int lr = tid >> 2;
    const int lc = (tid & 3) * 16;
    {
        const float* p = Qg + lr * 64 + lc;
        float4 v0 = *(const float4*)p;
        float4 v1 = *(const float4*)(p + 4);
        float4 v2 = *(const float4*)(p + 8);
        float4 v3 = *(const float4*)(p + 12);
        Qt[(lc + 0) * SP + lr] = v0.x;  Qt[(lc + 1) * SP + lr] = v0.y;
        Qt[(lc + 2) * SP + lr] = v0.z;  Qt[(lc + 3) * SP + lr] = v0.w;
        Qt[(lc + 4) * SP + lr] = v1.x;  Qt[(lc + 5) * SP + lr] = v1.y;
        Qt[(lc + 6) * SP + lr] = v1.z;  Qt[(lc + 7) * SP + lr] = v1.w;
        Qt[(lc + 8) * SP + lr] = v2.x;  Qt[(lc + 9) * SP + lr] = v2.y;
        Qt[(lc + 10) * SP + lr] = v2.z; Qt[(lc + 11) * SP + lr] = v2.w;
        Qt[(lc + 12) * SP + lr] = v3.x; Qt[(lc + 13) * SP + lr] = v3.y;
        Qt[(lc + 14) * SP + lr] = v3.z; Qt[(lc + 15) * SP + lr] = v3.w;
    }

    float m[4], l[4], o[4][4];
#pragma unroll
    for (int i = 0; i < 4; i++) {
        m[i] = -1e30f; l[i] = 0.0f;
#pragma unroll
        for (int j = 0; j < 4; j++) o[i][j] = 0.0f;
    }

    for (int kb = 0; kb <= qb; kb++) {
        const float* kp = Kg + (size_t)(kb * 64 + lr) * 64 + lc;
        const float* vp = Vg + (size_t)(kb * 64 + lr) * 64 + lc;
        float4 k0 = *(const float4*)kp;
        float4 k1 = *(const float4*)(kp + 4);
        float4 k2 = *(const float4*)(kp + 8);
        float4 k3 = *(const float4*)(kp + 12);
        float4 w0 = *(const float4*)vp;
        float4 w1 = *(const float4*)(vp + 4);
        float4 w2 = *(const float4*)(vp + 8);
        float4 w3 = *(const float4*)(vp + 12);
        __syncthreads();  // prior iteration done reading Kt/Vs/Pn
        Kt[(lc + 0) * SP + lr] = k0.x;  Kt[(lc + 1) * SP + lr] = k0.y;
        Kt[(lc + 2) * SP + lr] = k0.z;  Kt[(lc + 3) * SP + lr] = k0.w;
        Kt[(lc + 4) * SP + lr] = k1.x;  Kt[(lc + 5) * SP + lr] = k1.y;
        Kt[(lc + 6) * SP + lr] = k1.z;  Kt[(lc + 7) * SP + lr] = k1.w;
        Kt[(lc + 8) * SP + lr] = k2.x;  Kt[(lc + 9) * SP + lr] = k2.y;
        Kt[(lc + 10) * SP + lr] = k2.z; Kt[(lc + 11) * SP + lr] = k2.w;
        Kt[(lc + 12) * SP + lr] = k3.x; Kt[(lc + 13) * SP + lr] = k3.y;
        Kt[(lc + 14) * SP + lr] = k3.z; Kt[(lc + 15) * SP + lr] = k3.w;
        *(float4*)&Vs[lr * SP + lc]      = w0;
        *(float4*)&Vs[lr * SP + lc + 4]  = w1;
        *(float4*)&Vs[lr * SP + lc + 8]  = w2;
        *(float4*)&Vs[lr * SP + lc + 12] = w3;
        __syncthreads();

        // S = Q @ K^T   (scale+gain already folded into Q)
        float s[4][4];
#pragma unroll
        for (int i = 0; i < 4; i++)
#pragma unroll
            for (int j = 0; j < 4; j++) s[i][j] = 0.0f;
#pragma unroll 8
        for (int d = 0; d < 64; d++) {
            float qr[4], kr[4];
            *(float4*)qr = *(const float4*)&Qt[d * SP + 4 * ty];
            *(float4*)kr = *(const float4*)&Kt[d * SP + 4 * tx];
#pragma unroll
            for (int i = 0; i < 4; i++)
#pragma unroll
                for (int j = 0; j < 4; j++)
                    s[i][j] = fmaf(qr[i], kr[j], s[i][j]);
        }

        if (kb == qb) {
#pragma unroll
            for (int i = 0; i < 4; i++)
#pragma unroll
                for (int j = 0; j < 4; j++)
                    if (4 * tx + j > 4 * ty + i) s[i][j] = -1e30f;
        }

        // online softmax (rows owned by the 16 lanes sharing ty)
#pragma unroll
        for (int i = 0; i < 4; i++) {
            float mx = fmaxf(fmaxf(s[i][0], s[i][1]), fmaxf(s[i][2], s[i][3]));
#pragma unroll
            for (int off = 8; off > 0; off >>= 1)
                mx = fmaxf(mx, __shfl_xor_sync(0xffffffffu, mx, off));
            float mn = fmaxf(m[i], mx);
            float corr = __expf(m[i] - mn);
            float p0 = __expf(s[i][0] - mn);
            float p1 = __expf(s[i][1] - mn);
            float p2 = __expf(s[i][2] - mn);
            float p3 = __expf(s[i][3] - mn);
            float rs = p0 + p1 + p2 + p3;
#pragma unroll
            for (int off = 8; off > 0; off >>= 1)
                rs += __shfl_xor_sync(0xffffffffu, rs, off);
            l[i] = l[i] * corr + rs;
            m[i] = mn;
            o[i][0] *= corr; o[i][1] *= corr; o[i][2] *= corr; o[i][3] *= corr;
            *(float4*)&Pn[(4 * ty + i) * SP + 4 * tx] = make_float4(p0, p1, p2, p3);
        }
        __syncthreads();

        // O += P @ V
#pragma unroll 4
        for (int kk = 0; kk < 64; kk++) {
            float pr[4], vr[4];
            pr[0] = Pn[(4 * ty + 0) * SP + kk];
            pr[1] = Pn[(4 * ty + 1) * SP + kk];
            pr[2] = Pn[(4 * ty + 2) * SP + kk];
            pr[3] = Pn[(4 * ty + 3) * SP + kk];
            *(float4*)vr = *(const float4*)&Vs[kk * SP + 4 * tx];
#pragma unroll
            for (int i = 0; i < 4; i++)
#pragma unroll
                for (int j = 0; j < 4; j++)
                    o[i][j] = fmaf(pr[i], vr[j], o[i][j]);
        }
    }

#pragma unroll
    for (int i = 0; i < 4; i++) {
        float inv = 1.0f / l[i];
        int t = qb * 64 + 4 * ty + i;
        *(float4*)&g_y[(size_t)(b * T_ + t) * D_ + h * HD_ + 4 * tx] =
            make_float4(o[i][0] * inv, o[i][1] * inv, o[i][2] * inv, o[i][3] * inv);
    }
}

// ---------------- launch ----------------------------------------------------
extern "C" void kernel_launch(void* const* d_in, const int* in_sizes, int n_in,
                              void* d_out, int out_size) {
    const float* x    = (const float*)d_in[0];
    const float* Wq   = (const float*)d_in[1];
    const float* Wk   = (const float*)d_in[2];
    const float* Wv   = (const float*)d_in[3];
    const float* Wp   = (const float*)d_in[4];
    const float* gain = (const float*)d_in[5];
    float* out = (float*)d_out;

    k_freq<<<1, 32>>>();
    k_gemm_q<<<dim3(D_ / 128, BT_ / 128), 256>>>(x, Wq);
    k_gemm_kv<<<dim3(4, BT_ / 128), 256>>>(x, Wk, Wv);
    k_qprep<<<(B_ * T_ * H_) / 8, 256>>>(gain);
    k_kprep<<<(B_ * T_ * HKV_) / 8, 256>>>();
    k_vtrans<<<(B_ * HKV_ * T_ * 16) / 256, 256>>>();

    int flash_smem = 4 * 64 * SP * (int)sizeof(float);  // 69632 bytes
    cudaFuncSetAttribute(k_flash, cudaFuncAttributeMaxDynamicSharedMemorySize,
                         flash_smem);
    k_flash<<<dim3(T_ / 64, H_, B_), 256, flash_smem>>>();

    k_gemm_o<<<dim3(D_ / 128, BT_ / 128), 256>>>(Wp, out);
}

// round 4
// speedup vs baseline: 2.8508x; 1.8435x over previous
#include <cuda_runtime.h>
#include <math.h>

#define B_   2
#define T_   2048
#define D_   1024
#define H_   16
#define HKV_ 4
#define HD_  64
#define KV_  256
#define BT_  (B_ * T_)
#define EPS_ 1.1920928955078125e-07f
#define KT   32   // gemm K-tile
#define AST  36   // gemm smem row stride (tf32 words)
#define FST  68   // flash K/P smem stride (words)
#define VST  72   // flash V smem stride (words)

// ---------------- scratch (static device globals; no runtime alloc) --------
__device__ float g_qraw[BT_ * D_];          // [BT, 1024] raw q projection
__device__ float g_kraw[BT_ * KV_];         // [BT, 256]
__device__ float g_vraw[BT_ * KV_];         // [BT, 256]
__device__ float g_q[B_ * H_ * T_ * HD_];   // [B,H,T,hd] normed+rope+gain+scale
__device__ float g_k[B_ * HKV_ * T_ * HD_]; // [B,Hkv,T,hd] normed+rope
__device__ float g_v[B_ * HKV_ * T_ * HD_]; // [B,Hkv,T,hd]
__device__ float g_y[BT_ * D_];             // attention output [BT, 1024]
__device__ float g_invf[32];                // rope inv_freq table

// ---------------- inv_freq table (double pow once) -------------------------
__global__ void k_freq() {
    int i = threadIdx.x;
    if (i < 32) g_invf[i] = (float)pow(10000.0, -(double)i / 32.0);
}

// ---------------- tf32 helpers ---------------------------------------------
__device__ __forceinline__ unsigned f2tf(float f) {
    unsigned r;
    asm("cvt.rna.tf32.f32 %0, %1;" : "=r"(r) : "f"(f));
    return r;
}

__device__ __forceinline__ void mma_tf32(float c[4], unsigned a0, unsigned a1,
                                         unsigned a2, unsigned a3,
                                         unsigned b0, unsigned b1) {
    asm volatile(
        "mma.sync.aligned.m16n8k8.row.col.f32.tf32.tf32.f32 "
        "{%0,%1,%2,%3}, {%4,%5,%6,%7}, {%8,%9}, {%0,%1,%2,%3};"
        : "+f"(c[0]), "+f"(c[1]), "+f"(c[2]), "+f"(c[3])
        : "r"(a0), "r"(a1), "r"(a2), "r"(a3), "r"(b0), "r"(b1));
}

// ---------------- tf32 tensor-core GEMM: C[m,n] = sum_k A[m,k]*W[n,k] ------
// Block tile 128x128xKT(32), 256 threads = 8 warps (2M x 4N), warp 64x32.
__device__ __forceinline__ void gemm_tf32(const float* __restrict__ A,
                                          const float* __restrict__ W,
                                          float* __restrict__ C,
                                          int K, int N, int bm, int bn) {
    __shared__ unsigned As[128 * AST];
    __shared__ unsigned Ws[128 * AST];
    const int tid  = threadIdx.x;
    const int lane = tid & 31;
    const int w    = tid >> 5;
    const int g    = lane >> 2;     // 0..7
    const int tig  = lane & 3;      // 0..3
    const int wm   = (w & 1) * 64;  // warp M offset in tile
    const int wn   = (w >> 1) * 32; // warp N offset in tile

    const int lr  = tid >> 1;          // 0..127 loader row
    const int lcH = (tid & 1) * 16;    // loader col half
    const float* Ap = A + (size_t)(bm + lr) * K + lcH;
    const float* Wp = W + (size_t)(bn + lr) * K + lcH;

    float acc[4][4][4];
#pragma unroll
    for (int mi = 0; mi < 4; mi++)
#pragma unroll
        for (int ni = 0; ni < 4; ni++)
#pragma unroll
            for (int r = 0; r < 4; r++) acc[mi][ni][r] = 0.0f;

    for (int k0 = 0; k0 < K; k0 += KT) {
        float4 av[4], wv[4];
#pragma unroll
        for (int i = 0; i < 4; i++) {
            av[i] = *(const float4*)(Ap + k0 + 4 * i);
            wv[i] = *(const float4*)(Wp + k0 + 4 * i);
        }
        __syncthreads();
#pragma unroll
        for (int i = 0; i < 4; i++) {
            unsigned* pa = &As[lr * AST + lcH + 4 * i];
            pa[0] = f2tf(av[i].x); pa[1] = f2tf(av[i].y);
            pa[2] = f2tf(av[i].z); pa[3] = f2tf(av[i].w);
            unsigned* pw = &Ws[lr * AST + lcH + 4 * i];
            pw[0] = f2tf(wv[i].x); pw[1] = f2tf(wv[i].y);
            pw[2] = f2tf(wv[i].z); pw[3] = f2tf(wv[i].w);
        }
        __syncthreads();
#pragma unroll
        for (int ks = 0; ks < KT / 8; ks++) {
            unsigned bfr[4][2];
#pragma unroll
            for (int ni = 0; ni < 4; ni++) {
                int r = (wn + ni * 8 + g) * AST + ks * 8 + tig;
                bfr[ni][0] = Ws[r];
                bfr[ni][1] = Ws[r + 4];
            }
#pragma unroll
            for (int mi = 0; mi < 4; mi++) {
                int r = (wm + mi * 16 + g) * AST + ks * 8 + tig;
                unsigned a0 = As[r];
                unsigned a2 = As[r + 4];
                unsigned a1 = As[r + 8 * AST];
                unsigned a3 = As[r + 8 * AST + 4];
#pragma unroll
                for (int ni = 0; ni < 4; ni++)
                    mma_tf32(acc[mi][ni], a0, a1, a2, a3,
                             bfr[ni][0], bfr[ni][1]);
            }
        }
    }

#pragma unroll
    for (int mi = 0; mi < 4; mi++) {
#pragma unroll
        for (int ni = 0; ni < 4; ni++) {
            int row = bm + wm + mi * 16 + g;
            int col = bn + wn + ni * 8 + 2 * tig;
            *(float2*)&C[(size_t)row * N + col] =
                make_float2(acc[mi][ni][0], acc[mi][ni][1]);
            *(float2*)&C[(size_t)(row + 8) * N + col] =
                make_float2(acc[mi][ni][2], acc[mi][ni][3]);
        }
    }
}

__global__ void __launch_bounds__(256) k_gemm_q(const float* __restrict__ x,
                                                const float* __restrict__ W) {
    gemm_tf32(x, W, g_qraw, D_, D_, blockIdx.y * 128, blockIdx.x * 128);
}
// K and V projections fused into one launch (grid.x: 0,1 -> K ; 2,3 -> V)
__global__ void __launch_bounds__(256) k_gemm_kv(const float* __restrict__ x,
                                                 const float* __restrict__ Wk,
                                                 const float* __restrict__ Wv) {
    int bx = blockIdx.x;
    const float* W = (bx < 2) ? Wk : Wv;
    float* C = (bx < 2) ? g_kraw : g_vraw;
    int bn = (bx & 1) * 128;
    gemm_tf32(x, W, C, D_, KV_, blockIdx.y * 128, bn);
}
__global__ void __launch_bounds__(256) k_gemm_o(const float* __restrict__ W,
                                                float* __restrict__ out) {
    gemm_tf32(g_y, W, out, D_, D_, blockIdx.y * 128, blockIdx.x * 128);
}

// ---------------- RMSNorm + RoPE (+gain*scale for q), one warp per head ----
__global__ void __launch_bounds__(256) k_qprep(const float* __restrict__ gain) {
    int wid = (blockIdx.x * blockDim.x + threadIdx.x) >> 5;
    int lane = threadIdx.x & 31;
    int h = wid & (H_ - 1);
    int t = (wid >> 4) & (T_ - 1);
    int b = wid >> 15;
    const float* src = g_qraw + (size_t)(b * T_ + t) * D_ + h * HD_;
    float x1 = src[lane], x2 = src[lane + 32];
    float ss = x1 * x1 + x2 * x2;
#pragma unroll
    for (int o = 16; o > 0; o >>= 1) ss += __shfl_xor_sync(0xffffffffu, ss, o);
    float r = rsqrtf(ss * (1.0f / 64.0f) + EPS_);
    x1 *= r; x2 *= r;
    float f = (float)t * g_invf[lane];
    float s, c;
    sincosf(f, &s, &c);
    float g = gain[h] * 0.125f;  // fold attention scale hd^-0.5 into q
    float* dst = g_q + ((size_t)(b * H_ + h) * T_ + t) * HD_;
    dst[lane]      = (x1 * c + x2 * s) * g;
    dst[lane + 32] = (x2 * c - x1 * s) * g;
}

__global__ void __launch_bounds__(256) k_kprep() {
    int wid = (blockIdx.x * blockDim.x + threadIdx.x) >> 5;
    int lane = threadIdx.x & 31;
    int h = wid & (HKV_ - 1);
    int t = (wid >> 2) & (T_ - 1);
    int b = wid >> 13;
    const float* src = g_kraw + (size_t)(b * T_ + t) * KV_ + h * HD_;
    float x1 = src[lane], x2 = src[lane + 32];
    float ss = x1 * x1 + x2 * x2;
#pragma unroll
    for (int o = 16; o > 0; o >>= 1) ss += __shfl_xor_sync(0xffffffffu, ss, o);
    float r = rsqrtf(ss * (1.0f / 64.0f) + EPS_);
    x1 *= r; x2 *= r;
    float f = (float)t * g_invf[lane];
    float s, c;
    sincosf(f, &s, &c);
    float* dst = g_k + ((size_t)(b * HKV_ + h) * T_ + t) * HD_;
    dst[lane]      = x1 * c + x2 * s;
    dst[lane + 32] = x2 * c - x1 * s;
}

__global__ void __launch_bounds__(256) k_vtrans() {
    int i = blockIdx.x * blockDim.x + threadIdx.x;  // over B*HKV*T*16 float4s
    int d4 = i & 15;
    int t = (i >> 4) & (T_ - 1);
    int hk = (i >> 15) & (HKV_ - 1);
    int b = i >> 17;
    const float4* s = (const float4*)(g_vraw + (size_t)(b * T_ + t) * KV_ + hk * HD_) + d4;
    float4* d = (float4*)(g_v + ((size_t)(b * HKV_ + hk) * T_ + t) * HD_) + d4;
    *d = *s;
}

// ---------------- flash attention, tf32 mma, BQ=128 BN=64 ------------------
// 8 warps, warp w owns q-rows [w*16, w*16+16). Q a-frags resident.
extern __shared__ unsigned shf[];

__global__ void __launch_bounds__(256, 2) k_flash2() {
    unsigned* Ksh = shf;                       // [64][FST]
    unsigned* Vsh = shf + 64 * FST;            // [64][VST]
    unsigned* Psh = shf + 64 * FST + 64 * VST; // [128][FST]

    const int tid  = threadIdx.x;
    const int lane = tid & 31;
    const int w    = tid >> 5;
    const int g    = lane >> 2;   // 0..7
    const int tig  = lane & 3;    // 0..3
    const int wm   = w * 16;
    const int qb   = (int)gridDim.x - 1 - (int)blockIdx.x;  // heavy first
    const int h = blockIdx.y, b = blockIdx.z;
    const int hkv = h >> 2;

    const float* Qg = g_q + ((size_t)(b * H_ + h) * T_ + qb * 128) * HD_;
    const float* Kg = g_k + (size_t)(b * HKV_ + hkv) * T_ * HD_;
    const float* Vg = g_v + (size_t)(b * HKV_ + hkv) * T_ * HD_;

    // stage Q tile [128][64] into Psh (tf32), then load resident a-frags
    {
        int lr = tid >> 1;
        int lc = (tid & 1) * 32;
        const float* p = Qg + lr * 64 + lc;
#pragma unroll
        for (int i = 0; i < 8; i++) {
            float4 v = *(const float4*)(p + 4 * i);
            unsigned* d = &Psh[lr * FST + lc + 4 * i];
            d[0] = f2tf(v.x); d[1] = f2tf(v.y);
            d[2] = f2tf(v.z); d[3] = f2tf(v.w);
        }
    }
    __syncthreads();
    unsigned qa[8][4];
#pragma unroll
    for (int ks = 0; ks < 8; ks++) {
        qa[ks][0] = Psh[(wm + g) * FST + ks * 8 + tig];
        qa[ks][1] = Psh[(wm + g + 8) * FST + ks * 8 + tig];
        qa[ks][2] = Psh[(wm + g) * FST + ks * 8 + tig + 4];
        qa[ks][3] = Psh[(wm + g + 8) * FST + ks * 8 + tig + 4];
    }

    float m0 = -1e30f, m1 = -1e30f, l0 = 0.0f, l1 = 0.0f;
    float o[8][4];
#pragma unroll
    for (int nt = 0; nt < 8; nt++)
#pragma unroll
        for (int r = 0; r < 4; r++) o[nt][r] = 0.0f;

    const int lr  = tid >> 2;         // 0..63 kv loader row
    const int lc4 = (tid & 3) * 16;   // kv loader col
    const int nkb = 2 * qb + 2;

    for (int kb = 0; kb < nkb; kb++) {
        const float* kp = Kg + (size_t)(kb * 64 + lr) * 64 + lc4;
        const float* vp = Vg + (size_t)(kb * 64 + lr) * 64 + lc4;
        float4 kv[4], vv[4];
#pragma unroll
        for (int i = 0; i < 4; i++) {
            kv[i] = *(const float4*)(kp + 4 * i);
            vv[i] = *(const float4*)(vp + 4 * i);
        }
        __syncthreads();  // prior iter's mma reads of Ksh/Vsh complete
#pragma unroll
        for (int i = 0; i < 4; i++) {
            unsigned* dk = &Ksh[lr * FST + lc4 + 4 * i];
            dk[0] = f2tf(kv[i].x); dk[1] = f2tf(kv[i].y);
            dk[2] = f2tf(kv[i].z); dk[3] = f2tf(kv[i].w);
            unsigned* dv = &Vsh[lr * VST + lc4 + 4 * i];
            dv[0] = f2tf(vv[i].x); dv[1] = f2tf(vv[i].y);
            dv[2] = f2tf(vv[i].z); dv[3] = f2tf(vv[i].w);
        }
        __syncthreads();

        // S = Q @ K^T : per warp 16x64
        float s[8][4];
#pragma unroll
        for (int nt = 0; nt < 8; nt++)
#pragma unroll
            for (int r = 0; r < 4; r++) s[nt][r] = 0.0f;
#pragma unroll
        for (int ks = 0; ks < 8; ks++) {
#pragma unroll
            for (int nt = 0; nt < 8; nt++) {
                int base = (nt * 8 + g) * FST + ks * 8 + tig;
                mma_tf32(s[nt], qa[ks][0], qa[ks][1], qa[ks][2], qa[ks][3],
                         Ksh[base], Ksh[base + 4]);
            }
        }

        // causal mask (only the two diagonal-touching key blocks)
        if (kb >= 2 * qb) {
            int row0 = qb * 128 + wm + g;
            int row1 = row0 + 8;
#pragma unroll
            for (int nt = 0; nt < 8; nt++) {
                int col = kb * 64 + nt * 8 + 2 * tig;
                if (col > row0)     s[nt][0] = -1e30f;
                if (col + 1 > row0) s[nt][1] = -1e30f;
                if (col > row1)     s[nt][2] = -1e30f;
                if (col + 1 > row1) s[nt][3] = -1e30f;
            }
        }

        // online softmax: row g (s[.][0..1]) and row g+8 (s[.][2..3])
        float mx0 = -1e30f, mx1 = -1e30f;
#pragma unroll
        for (int nt = 0; nt < 8; nt++) {
            mx0 = fmaxf(mx0, fmaxf(s[nt][0], s[nt][1]));
            mx1 = fmaxf(mx1, fmaxf(s[nt][2], s[nt][3]));
        }
        mx0 = fmaxf(mx0, __shfl_xor_sync(0xffffffffu, mx0, 1));
        mx0 = fmaxf(mx0, __shfl_xor_sync(0xffffffffu, mx0, 2));
        mx1 = fmaxf(mx1, __shfl_xor_sync(0xffffffffu, mx1, 1));
        mx1 = fmaxf(mx1, __shfl_xor_sync(0xffffffffu, mx1, 2));
        float nm0 = fmaxf(m0, mx0), nm1 = fmaxf(m1, mx1);
        float c0 = __expf(m0 - nm0), c1 = __expf(m1 - nm1);
        float rs0 = 0.0f, rs1 = 0.0f;
#pragma unroll
        for (int nt = 0; nt < 8; nt++) {
            s[nt][0] = __expf(s[nt][0] - nm0);
            s[nt][1] = __expf(s[nt][1] - nm0);
            s[nt][2] = __expf(s[nt][2] - nm1);
            s[nt][3] = __expf(s[nt][3] - nm1);
            rs0 += s[nt][0] + s[nt][1];
            rs1 += s[nt][2] + s[nt][3];
        }
        rs0 += __shfl_xor_sync(0xffffffffu, rs0, 1);
        rs0 += __shfl_xor_sync(0xffffffffu, rs0, 2);
        rs1 += __shfl_xor_sync(0xffffffffu, rs1, 1);
        rs1 += __shfl_xor_sync(0xffffffffu, rs1, 2);
        l0 = l0 * c0 + rs0;
        l1 = l1 * c1 + rs1;
        m0 = nm0; m1 = nm1;
#pragma unroll
        for (int nt = 0; nt < 8; nt++) {
            o[nt][0] *= c0; o[nt][1] *= c0;
            o[nt][2] *= c1; o[nt][3] *= c1;
        }

        // store P fragments (tf32) to own warp's rows; warp-local sync only
#pragma unroll
        for (int nt = 0; nt < 8; nt++) {
            int col = nt * 8 + 2 * tig;
            *(uint2*)&Psh[(wm + g) * FST + col] =
                make_uint2(f2tf(s[nt][0]), f2tf(s[nt][1]));
            *(uint2*)&Psh[(wm + g + 8) * FST + col] =
                make_uint2(f2tf(s[nt][2]), f2tf(s[nt][3]));
        }
        __syncwarp();

        // O += P @ V
#pragma unroll
        for (int ks = 0; ks < 8; ks++) {
            unsigned a0 = Psh[(wm + g) * FST + ks * 8 + tig];
            unsigned a1 = Psh[(wm + g + 8) * FST + ks * 8 + tig];
            unsigned a2 = Psh[(wm + g) * FST + ks * 8 + tig + 4];
            unsigned a3 = Psh[(wm + g + 8) * FST + ks * 8 + tig + 4];
#pragma unroll
            for (int nt = 0; nt < 8; nt++) {
                int base = (ks * 8 + tig) * VST + nt * 8 + g;
                mma_tf32(o[nt], a0, a1, a2, a3,
                         Vsh[base], Vsh[base + 4 * VST]);
            }
        }
    }

    float inv0 = 1.0f / l0, inv1 = 1.0f / l1;
    int r0 = qb * 128 + wm + g;
    int r1 = r0 + 8;
#pragma unroll
    for (int nt = 0; nt < 8; nt++) {
        int col = h * HD_ + nt * 8 + 2 * tig;
        *(float2*)&g_y[(size_t)(b * T_ + r0) * D_ + col] =
            make_float2(o[nt][0] * inv0, o[nt][1] * inv0);
        *(float2*)&g_y[(size_t)(b * T_ + r1) * D_ + col] =
            make_float2(o[nt][2] * inv1, o[nt][3] * inv1);
    }
}

// ---------------- launch ----------------------------------------------------
extern "C" void kernel_launch(void* const* d_in, const int* in_sizes, int n_in,
                              void* d_out, int out_size) {
    const float* x    = (const float*)d_in[0];
    const float* Wq   = (const float*)d_in[1];
    const float* Wk   = (const float*)d_in[2];
    const float* Wv   = (const float*)d_in[3];
    const float* Wp   = (const float*)d_in[4];
    const float* gain = (const float*)d_in[5];
    float* out = (float*)d_out;

    k_freq<<<1, 32>>>();
    k_gemm_q<<<dim3(D_ / 128, BT_ / 128), 256>>>(x, Wq);
    k_gemm_kv<<<dim3(4, BT_ / 128), 256>>>(x, Wk, Wv);
    k_qprep<<<(B_ * T_ * H_) / 8, 256>>>(gain);
    k_kprep<<<(B_ * T_ * HKV_) / 8, 256>>>();
    k_vtrans<<<(B_ * HKV_ * T_ * 16) / 256, 256>>>();

    int flash_smem = (64 * FST + 64 * VST + 128 * FST) * (int)sizeof(unsigned);
    cudaFuncSetAttribute(k_flash2, cudaFuncAttributeMaxDynamicSharedMemorySize,
                         flash_smem);
    k_flash2<<<dim3(T_ / 128, H_, B_), 256, flash_smem>>>();

    k_gemm_o<<<dim3(D_ / 128, BT_ / 128), 256>>>(Wp, out);
}